// round 6
// baseline (speedup 1.0000x reference)
#include <cuda_runtime.h>
#include <cstdint>
#include <math.h>

// Problem constants
#define N_TOT 65536          // 64*32*32 rows
#define D_DIM 64
#define K_EMB 1024
#define TPB 256
#define ROWS_PER_TILE 64     // rows per block; 4 k-quarters per row
#define NTILE (N_TOT / ROWS_PER_TILE)   // 1024 blocks
#define KC 128               // emb rows per smem chunk (32KB)
#define NCHUNK (K_EMB / KC)  // 8
#define KQ (KC / 4)          // 32 k per thread per chunk

// Output layout: loss(1), quant_out(64*64*32*32), perplexity(1),
// encodings(65536*1024), idx(65536)   — all float32, concatenated.
#define OFF_LOSS 0
#define OFF_Q    1
#define OFF_PERP 4194305
#define OFF_ENC  4194306ll
#define OFF_IDX  71303170ll

// Scratch (no device allocation allowed -> __device__ globals)
__device__ float g_embss[K_EMB];
__device__ float g_partial[NTILE];

// ---- packed f32x2 helpers (Blackwell FFMA2 path) ----
__device__ __forceinline__ unsigned long long pack2(float lo, float hi) {
    unsigned long long r;
    asm("mov.b64 %0, {%1,%2};" : "=l"(r) : "f"(lo), "f"(hi));
    return r;
}
__device__ __forceinline__ void unpack2(unsigned long long v, float& lo, float& hi) {
    asm("mov.b64 {%0,%1}, %2;" : "=f"(lo), "=f"(hi) : "l"(v));
}
__device__ __forceinline__ unsigned long long fma2(unsigned long long a,
                                                   unsigned long long b,
                                                   unsigned long long c) {
    unsigned long long d;
    asm("fma.rn.f32x2 %0, %1, %2, %3;" : "=l"(d) : "l"(a), "l"(b), "l"(c));
    return d;
}
__device__ __forceinline__ unsigned long long add2(unsigned long long a,
                                                   unsigned long long b) {
    unsigned long long d;
    asm("add.rn.f32x2 %0, %1, %2;" : "=l"(d) : "l"(a), "l"(b));
    return d;
}

// ---- init: per-codeword squared norms (bit-identical rounding to prior pass) ----
__global__ void vq_init(const float* __restrict__ emb) {
    int k = blockIdx.x * 64 + threadIdx.x;    // grid 16 x 64 -> 1024 rows
    const float* e = emb + (size_t)k * D_DIM;
    float s = 0.f;
#pragma unroll
    for (int d = 0; d < D_DIM; d++) s = fmaf(e[d], e[d], s);
    g_embss[k] = s;
}

// ---- main: argmin (k-split x4) + quant + one-hot + idx + mse partials ----
__global__ __launch_bounds__(TPB, 2)
void vq_main(const float* __restrict__ x,
             const float* __restrict__ emb,
             float* __restrict__ out) {
    __shared__ float esm[KC * D_DIM];   // 32 KB emb chunk, [k][d] row-major
    __shared__ float ess[KC];           // chunk squared norms
    __shared__ float sd[TPB];           // merge dists / mse reduction
    __shared__ int   si[TPB];           // merge indices

    const int t  = threadIdx.x;
    const int r  = t & 63;              // row within tile (warp-uniform q)
    const int q  = t >> 6;              // k-quarter 0..3
    const int n0 = blockIdx.x * ROWS_PER_TILE;
    const int b  = n0 >> 10;            // n = b*1024 + hw
    const int hw = (n0 & 1023) + r;
    const float* xbase = x + (size_t)b * 65536;   // inputs[b, d, h, w]

    // Load this thread's row of x as f32x2 pairs; row sum-of-squares (same
    // rounding order as the passing kernel).
    unsigned long long x2[32];
    float A = 0.f;
#pragma unroll
    for (int i = 0; i < 32; i++) {
        float a0 = xbase[(2 * i) * 1024 + hw];
        float a1 = xbase[(2 * i + 1) * 1024 + hw];
        A = fmaf(a0, a0, A);
        A = fmaf(a1, a1, A);
        x2[i] = pack2(a0, a1);
    }

    float bestd = 3.4e38f;
    int   besti = 0;

    for (int kc = 0; kc < NCHUNK; kc++) {
        // Cooperative chunk load (coalesced float4)
        {
            const float4* src = (const float4*)(emb + (size_t)kc * KC * D_DIM);
            float4* dst = (float4*)esm;
#pragma unroll
            for (int i = 0; i < (KC * D_DIM / 4) / TPB; i++)   // 8 iters
                dst[t + i * TPB] = src[t + i * TPB];
            if (t < KC) ess[t] = g_embss[kc * KC + t];
        }
        __syncthreads();

        const int kb = q * KQ;          // this quarter's k range in the chunk
#pragma unroll 4
        for (int k = kb; k < kb + KQ; k++) {
            const ulonglong2* e2 = (const ulonglong2*)(esm + k * D_DIM);
            unsigned long long a0 = 0ull, a1 = 0ull;
#pragma unroll
            for (int j = 0; j < 16; j++) {      // 16 LDS.128 + 32 FFMA2
                ulonglong2 ev = e2[j];          // warp-broadcast
                a0 = fma2(x2[2 * j],     ev.x, a0);
                a1 = fma2(x2[2 * j + 1], ev.y, a1);
            }
            float lo, hi;
            unpack2(add2(a0, a1), lo, hi);
            float c = lo + hi;
            // dist = fl(fl(A + ||e||^2) - fl(2*C))  -- mirror reference expr
            float d = __fsub_rn(__fadd_rn(A, ess[k]), 2.f * c);
            int kk = kc * KC + k;
            if (d < bestd) { bestd = d; besti = kk; }   // first-index ties
        }
        __syncthreads();
    }

    // Merge the 4 k-quarter candidates per row (lexicographic (d, k) min
    // == global first-index argmin since per-thread scans are k-ascending).
    sd[t] = bestd;
    si[t] = besti;
    __syncthreads();

    float mse = 0.f;
    if (t < 64) {                       // q==0 threads own the row epilogue
#pragma unroll
        for (int qq = 1; qq < 4; qq++) {
            float d2 = sd[t + 64 * qq];
            int   i2 = si[t + 64 * qq];
            if (d2 < bestd || (d2 == bestd && i2 < besti)) { bestd = d2; besti = i2; }
        }
        const int n = n0 + t;
        out[OFF_IDX + n] = (float)besti;
        out[OFF_ENC + (long long)n * K_EMB + besti] = 1.0f;

        const float* e = emb + (size_t)besti * D_DIM;
        float* qo = out + OFF_Q + (size_t)b * 65536;    // NCHW quant_out
#pragma unroll
        for (int i = 0; i < 32; i++) {
            float v0 = __ldg(e + 2 * i), v1 = __ldg(e + 2 * i + 1);
            qo[(2 * i) * 1024 + hw]     = v0;           // coalesced over hw
            qo[(2 * i + 1) * 1024 + hw] = v1;
            float xl, xh;
            unpack2(x2[i], xl, xh);
            float d0 = v0 - xl, d1 = v1 - xh;
            mse = fmaf(d0, d0, mse);
            mse = fmaf(d1, d1, mse);
        }
    }
    __syncthreads();                    // protect sd reuse

    // Deterministic block-tree reduction of squared error
    sd[t] = mse;
    __syncthreads();
    for (int s = TPB / 2; s > 0; s >>= 1) {
        if (t < s) sd[t] += sd[t + s];
        __syncthreads();
    }
    if (t == 0) g_partial[blockIdx.x] = sd[0];
}

// ---- final: histogram from idx + loss + perplexity (parallel, deterministic) ----
__global__ void vq_final(float* __restrict__ out) {
    __shared__ int   hist[K_EMB];
    __shared__ float red[1024];
    const int t = threadIdx.x;          // 1024 threads

    hist[t] = 0;
    __syncthreads();

    const float* idxp = out + OFF_IDX;
#pragma unroll 8
    for (int i = 0; i < N_TOT / 1024; i++) {       // 64 coalesced reads
        int v = (int)idxp[t + i * 1024];
        atomicAdd(&hist[v], 1);
    }

    // MSE total (tree over 1024 block partials)
    red[t] = g_partial[t];
    __syncthreads();                     // also orders the smem atomics above
    for (int s = 512; s > 0; s >>= 1) {
        if (t < s) red[t] += red[t + s];
        __syncthreads();
    }
    float mse_total = red[0];
    __syncthreads();

    // Entropy (tree over 1024 codewords)
    float p = (float)hist[t] / (float)N_TOT;
    red[t] = p * logf(p + 1e-10f);
    __syncthreads();
    for (int s = 512; s > 0; s >>= 1) {
        if (t < s) red[t] += red[t + s];
        __syncthreads();
    }

    if (t == 0) {
        float H = red[0];
        float perp = expf(-H);
        float mse = mse_total / (float)(N_TOT * D_DIM);
        // q_latent_loss == e_latent_loss numerically (stop_gradient is identity fwd)
        float loss = mse * 1.25f + 0.1f * ((float)K_EMB - perp) / (float)K_EMB;
        out[OFF_LOSS] = loss;
        out[OFF_PERP] = perp;
    }
}

extern "C" void kernel_launch(void* const* d_in, const int* in_sizes, int n_in,
                              void* d_out, int out_size) {
    const float* xin = (const float*)d_in[0];
    const float* emb = (const float*)d_in[1];
    // inputs (4194304 elems) is larger than emb (65536 elems); guard ordering
    if (n_in >= 2 && in_sizes[0] < in_sizes[1]) {
        const float* tmp = xin; xin = emb; emb = tmp;
    }
    float* out = (float*)d_out;

    vq_init<<<16, 64>>>(emb);
    cudaMemsetAsync(out + OFF_ENC, 0, (size_t)N_TOT * K_EMB * sizeof(float), 0);
    vq_main<<<NTILE, TPB>>>(xin, emb, out);
    vq_final<<<1, 1024>>>(out);
}

// round 7
// speedup vs baseline: 1.7720x; 1.7720x over previous
#include <cuda_runtime.h>
#include <cstdint>
#include <math.h>

// Problem constants
#define N_TOT 65536          // 64*32*32 rows
#define D_DIM 64
#define K_EMB 1024
#define TPB 256
#define ROWS_PER_BLOCK 512   // 2 rows per thread
#define NBLK (N_TOT / ROWS_PER_BLOCK)   // 128
#define KC 128               // emb rows per smem chunk (32KB)
#define NCHUNK (K_EMB / KC)  // 8
#define FILL_ROWS (ROWS_PER_BLOCK / NCHUNK)   // 64 enc rows zero-filled per chunk

// Output layout: loss(1), quant_out(64*64*32*32), perplexity(1),
// encodings(65536*1024), idx(65536)   — all float32, concatenated.
#define OFF_LOSS 0
#define OFF_Q    1
#define OFF_PERP 4194305
#define OFF_ENC  4194306ll
#define OFF_IDX  71303170ll

// Scratch (no device allocation allowed -> __device__ globals)
__device__ float g_embss[K_EMB];
__device__ float g_partial[NBLK];

// ---- packed f32x2 helpers (Blackwell FFMA2 path) ----
__device__ __forceinline__ unsigned long long pack2(float lo, float hi) {
    unsigned long long r;
    asm("mov.b64 %0, {%1,%2};" : "=l"(r) : "f"(lo), "f"(hi));
    return r;
}
__device__ __forceinline__ void unpack2(unsigned long long v, float& lo, float& hi) {
    asm("mov.b64 {%0,%1}, %2;" : "=f"(lo), "=f"(hi) : "l"(v));
}
__device__ __forceinline__ unsigned long long fma2(unsigned long long a,
                                                   unsigned long long b,
                                                   unsigned long long c) {
    unsigned long long d;
    asm("fma.rn.f32x2 %0, %1, %2, %3;" : "=l"(d) : "l"(a), "l"(b), "l"(c));
    return d;
}
__device__ __forceinline__ unsigned long long add2(unsigned long long a,
                                                   unsigned long long b) {
    unsigned long long d;
    asm("add.rn.f32x2 %0, %1, %2;" : "=l"(d) : "l"(a), "l"(b));
    return d;
}

// ---- init: per-codeword squared norms (bit-identical rounding chain) ----
__global__ void vq_init(const float* __restrict__ emb) {
    int k = blockIdx.x * blockDim.x + threadIdx.x;   // 8 x 128 -> 1024 rows
    const float4* e4 = (const float4*)(emb + (size_t)k * D_DIM);
    float s = 0.f;
#pragma unroll
    for (int i = 0; i < D_DIM / 4; i++) {            // 16 LDG.128, MLP-friendly
        float4 v = __ldg(e4 + i);
        s = fmaf(v.x, v.x, s);                       // same d-ascending fmaf chain
        s = fmaf(v.y, v.y, s);
        s = fmaf(v.z, v.z, s);
        s = fmaf(v.w, v.w, s);
    }
    g_embss[k] = s;
}

// ---- main: argmin + enc zero-fill + quant + one-hot + idx + mse partials ----
__global__ __launch_bounds__(TPB, 1)
void vq_main(const float* __restrict__ x,
             const float* __restrict__ emb,
             float* __restrict__ out) {
    __shared__ float esm[KC * D_DIM];   // 32 KB emb chunk, [k][d] row-major
    __shared__ float ess[KC];           // chunk squared norms
    __shared__ float red[TPB];

    const int t  = threadIdx.x;
    const int n0 = blockIdx.x * ROWS_PER_BLOCK;   // 512 rows, single batch b
    const int b  = n0 >> 10;                      // n = b*1024 + hw
    const int hw_a = (n0 & 1023) + t;
    const int hw_b = hw_a + TPB;
    const float* xbase = x + (size_t)b * 65536;   // inputs[b, d, h, w]

    // Load 2 rows of x into registers as f32x2 pairs; row sum-of-squares.
    unsigned long long xa2[32], xb2[32];
    float Aa = 0.f, Ab = 0.f;
#pragma unroll
    for (int i = 0; i < 32; i++) {
        float a0 = xbase[(2 * i) * 1024 + hw_a];
        float a1 = xbase[(2 * i + 1) * 1024 + hw_a];
        Aa = fmaf(a0, a0, Aa);
        Aa = fmaf(a1, a1, Aa);
        xa2[i] = pack2(a0, a1);
        float b0 = xbase[(2 * i) * 1024 + hw_b];
        float b1 = xbase[(2 * i + 1) * 1024 + hw_b];
        Ab = fmaf(b0, b0, Ab);
        Ab = fmaf(b1, b1, Ab);
        xb2[i] = pack2(b0, b1);
    }

    float bestd_a = 3.4e38f, bestd_b = 3.4e38f;
    int   besti_a = 0,       besti_b = 0;

    for (int kc = 0; kc < NCHUNK; kc++) {
        // Zero-fill a 64-row slice of the encodings output (replaces the
        // serial 268MB cudaMemset graph node; stores drain under the fma
        // work of this chunk). float2: OFF_ENC is only 8B-aligned.
        {
            const float2 z = make_float2(0.f, 0.f);
            float2* ep = (float2*)(out + OFF_ENC +
                                   (long long)(n0 + kc * FILL_ROWS) * K_EMB) + t;
#pragma unroll 4
            for (int row = 0; row < FILL_ROWS; row++) {
                ep[0]   = z;                       // cols 2t, 2t+1
                ep[TPB] = z;                       // cols 512+2t, 513+2t
                ep += K_EMB / 2;
            }
        }

        // Cooperative chunk load (coalesced float4)
        {
            const float4* src = (const float4*)(emb + (size_t)kc * KC * D_DIM);
            float4* dst = (float4*)esm;
#pragma unroll
            for (int i = 0; i < (KC * D_DIM / 4) / TPB; i++)   // 8 iters
                dst[t + i * TPB] = src[t + i * TPB];
            if (t < KC) ess[t] = g_embss[kc * KC + t];
        }
        __syncthreads();

        for (int k = 0; k < KC; k++) {
            const ulonglong2* e2 = (const ulonglong2*)(esm + k * D_DIM);
            unsigned long long aa0 = 0ull, aa1 = 0ull, ab0 = 0ull, ab1 = 0ull;
#pragma unroll
            for (int j = 0; j < 16; j++) {          // 16 LDS.128 + 64 FFMA2
                ulonglong2 ev = e2[j];              // broadcast across warp
                aa0 = fma2(xa2[2 * j],     ev.x, aa0);
                aa1 = fma2(xa2[2 * j + 1], ev.y, aa1);
                ab0 = fma2(xb2[2 * j],     ev.x, ab0);
                ab1 = fma2(xb2[2 * j + 1], ev.y, ab1);
            }
            float lo, hi;
            unsigned long long sa = add2(aa0, aa1);
            unpack2(sa, lo, hi);
            float ca = lo + hi;
            unsigned long long sb = add2(ab0, ab1);
            unpack2(sb, lo, hi);
            float cb = lo + hi;

            // dist = fl(fl(A + ||e||^2) - fl(2*C))  -- mirror reference expr
            float ek = ess[k];
            float da = __fsub_rn(__fadd_rn(Aa, ek), 2.f * ca);
            float db = __fsub_rn(__fadd_rn(Ab, ek), 2.f * cb);
            int kk = kc * KC + k;
            if (da < bestd_a) { bestd_a = da; besti_a = kk; }  // first-index ties
            if (db < bestd_b) { bestd_b = db; besti_b = kk; }
        }
        __syncthreads();
    }

    // ---- epilogue ----
    const int n_a = n0 + t;
    const int n_b = n_a + TPB;

    // Order the 1.0 scatters after this block's zero-fill stores (bar.sync
    // drains and orders prior global stores CTA-wide; rows are block-private).
    __syncthreads();

    out[OFF_IDX + n_a] = (float)besti_a;
    out[OFF_IDX + n_b] = (float)besti_b;
    out[OFF_ENC + (long long)n_a * K_EMB + besti_a] = 1.0f;
    out[OFF_ENC + (long long)n_b * K_EMB + besti_b] = 1.0f;

    float mse = 0.f;
    {
        const float* ea = emb + (size_t)besti_a * D_DIM;
        const float* eb = emb + (size_t)besti_b * D_DIM;
        float* q = out + OFF_Q + (size_t)b * 65536;   // NCHW quant_out
#pragma unroll
        for (int i = 0; i < 32; i++) {
            float xlo, xhi;
            float va0 = __ldg(ea + 2 * i), va1 = __ldg(ea + 2 * i + 1);
            q[(2 * i) * 1024 + hw_a]     = va0;       // coalesced over hw
            q[(2 * i + 1) * 1024 + hw_a] = va1;
            unpack2(xa2[i], xlo, xhi);
            float d0 = va0 - xlo, d1 = va1 - xhi;
            mse = fmaf(d0, d0, mse);
            mse = fmaf(d1, d1, mse);

            float vb0 = __ldg(eb + 2 * i), vb1 = __ldg(eb + 2 * i + 1);
            q[(2 * i) * 1024 + hw_b]     = vb0;
            q[(2 * i + 1) * 1024 + hw_b] = vb1;
            unpack2(xb2[i], xlo, xhi);
            d0 = vb0 - xlo; d1 = vb1 - xhi;
            mse = fmaf(d0, d0, mse);
            mse = fmaf(d1, d1, mse);
        }
    }

    // Deterministic block-tree reduction of squared error
    red[t] = mse;
    __syncthreads();
    for (int s = TPB / 2; s > 0; s >>= 1) {
        if (t < s) red[t] += red[t + s];
        __syncthreads();
    }
    if (t == 0) g_partial[blockIdx.x] = red[0];
}

// ---- final: histogram from idx + loss + perplexity (parallel, deterministic) ----
__global__ void vq_final(float* __restrict__ out) {
    __shared__ int   hist[K_EMB];
    __shared__ float red[1024];
    const int t = threadIdx.x;          // 1024 threads

    hist[t] = 0;
    __syncthreads();

    const float* idxp = out + OFF_IDX;
#pragma unroll 8
    for (int i = 0; i < N_TOT / 1024; i++) {       // 64 coalesced reads
        int v = (int)idxp[t + i * 1024];
        atomicAdd(&hist[v], 1);
    }

    // MSE total (tree over the 128 block partials)
    red[t] = (t < NBLK) ? g_partial[t] : 0.f;
    __syncthreads();                     // also orders the smem atomics above
    for (int s = 512; s > 0; s >>= 1) {
        if (t < s) red[t] += red[t + s];
        __syncthreads();
    }
    float mse_total = red[0];
    __syncthreads();

    // Entropy (tree over 1024 codewords)
    float p = (float)hist[t] / (float)N_TOT;
    red[t] = p * logf(p + 1e-10f);
    __syncthreads();
    for (int s = 512; s > 0; s >>= 1) {
        if (t < s) red[t] += red[t + s];
        __syncthreads();
    }

    if (t == 0) {
        float H = red[0];
        float perp = expf(-H);
        float mse = mse_total / (float)(N_TOT * D_DIM);
        // q_latent_loss == e_latent_loss numerically (stop_gradient is identity fwd)
        float loss = mse * 1.25f + 0.1f * ((float)K_EMB - perp) / (float)K_EMB;
        out[OFF_LOSS] = loss;
        out[OFF_PERP] = perp;
    }
}

extern "C" void kernel_launch(void* const* d_in, const int* in_sizes, int n_in,
                              void* d_out, int out_size) {
    const float* xin = (const float*)d_in[0];
    const float* emb = (const float*)d_in[1];
    // inputs (4194304 elems) is larger than emb (65536 elems); guard ordering
    if (n_in >= 2 && in_sizes[0] < in_sizes[1]) {
        const float* tmp = xin; xin = emb; emb = tmp;
    }
    float* out = (float*)d_out;

    vq_init<<<8, 128>>>(emb);
    vq_main<<<NBLK, TPB>>>(xin, emb, out);
    vq_final<<<1, 1024>>>(out);
}